// round 4
// baseline (speedup 1.0000x reference)
#include <cuda_runtime.h>

// AnnularDilatedKNN: B=4, N=4096, C=64, SAMPLE=16, DILATED_RATE=2 -> NSAMPLE=32, K_out=16
// radius^2 = 256.
//
// R3 changes:
//  - prep fused into query's smem staging (raw xyz -> SoA + sq in-block)
//  - query: 3-stage speculative pipeline. Per chunk: loads for base+256,
//    eval+ballots for base+128 (speculative, warp-uniform -> safe), bookkeeping
//    for base. Loop-carried chain reduced to popc-sum+setp+bra (~45cyc).
//  - gather: thread per (b,n,k4); int4 id loads, float4 reads AND float4
//    transposed writes (memory instr count ~2.4x lower).
// Per-candidate arithmetic + extraction bookkeeping byte-identical to the
// rel_err=0.0 verified kernels.

#define NB   4
#define NP   4096
#define KOUT 16

__device__ int g_ids[NB * NP * KOUT];

__device__ __forceinline__ float sq3(float x, float y, float z) {
    // jnp.sum(xyz*xyz, -1): left-to-right, separately rounded products (no fma).
    return __fadd_rn(__fadd_rn(__fmul_rn(x, x), __fmul_rn(y, y)), __fmul_rn(z, z));
}

// nib evaluation: byte-identical arithmetic to the verified kernels.
__device__ __forceinline__ unsigned eval_nib(float xn, float yn, float zn, float sqn,
                                             const float4& x4, const float4& y4,
                                             const float4& z4, const float4& s4) {
    unsigned nib = 0;
    float dot, d2;
    dot = fmaf(zn, z4.x, fmaf(yn, y4.x, __fmul_rn(xn, x4.x)));
    d2  = __fsub_rn(__fadd_rn(sqn, s4.x), __fmul_rn(2.0f, dot));
    if (d2 < 256.0f) nib |= 1u;
    dot = fmaf(zn, z4.y, fmaf(yn, y4.y, __fmul_rn(xn, x4.y)));
    d2  = __fsub_rn(__fadd_rn(sqn, s4.y), __fmul_rn(2.0f, dot));
    if (d2 < 256.0f) nib |= 2u;
    dot = fmaf(zn, z4.z, fmaf(yn, y4.z, __fmul_rn(xn, x4.z)));
    d2  = __fsub_rn(__fadd_rn(sqn, s4.z), __fmul_rn(2.0f, dot));
    if (d2 < 256.0f) nib |= 4u;
    dot = fmaf(zn, z4.w, fmaf(yn, y4.w, __fmul_rn(xn, x4.w)));
    d2  = __fsub_rn(__fadd_rn(sqn, s4.w), __fmul_rn(2.0f, dot));
    if (d2 < 256.0f) nib |= 8u;
    return nib;
}

// Bookkeeping for one chunk. Returns true when >=31 hits found (uniform).
__device__ __forceinline__ bool bookkeep(int base, int lane, unsigned lmask,
                                         unsigned nib, unsigned b0, unsigned b1,
                                         unsigned b2, unsigned b3,
                                         int& cnt, int* hits) {
    if (nib) {
        int p = cnt + __popc(b0 & lmask) + __popc(b1 & lmask)
                    + __popc(b2 & lmask) + __popc(b3 & lmask);
        const int c0 = base + (lane << 2);
        if (nib & 1u) { if (p < 31) hits[p] = c0;     ++p; }
        if (nib & 2u) { if (p < 31) hits[p] = c0 + 1; ++p; }
        if (nib & 4u) { if (p < 31) hits[p] = c0 + 2; ++p; }
        if (nib & 8u) { if (p < 31) hits[p] = c0 + 3; ++p; }
    }
    cnt += __popc(b0) + __popc(b1) + __popc(b2) + __popc(b3);
    return cnt >= 31;
}

__global__ __launch_bounds__(256) void query_kernel(const float* __restrict__ xyz) {
    extern __shared__ float sm[];
    float* sx  = sm;
    float* sy  = sm + NP;
    float* sz  = sm + 2 * NP;
    float* ssq = sm + 3 * NP;
    __shared__ int sh_hits[8][32];

    const int warp = threadIdx.x >> 5;
    const int lane = threadIdx.x & 31;
    const int q = (blockIdx.x << 3) + warp;      // global query id
    const int b = q >> 12;                        // all warps of a block share b
    const int n = q & (NP - 1);

    // Stage batch SoA + sq straight from raw xyz [N,3] (fused prep).
    {
        const float4* raw = reinterpret_cast<const float4*>(xyz) + b * (NP * 3 / 4);
        float4* tx = reinterpret_cast<float4*>(sx);
        float4* ty = reinterpret_cast<float4*>(sy);
        float4* tz = reinterpret_cast<float4*>(sz);
        float4* ts = reinterpret_cast<float4*>(ssq);
        for (int i = threadIdx.x; i < NP / 4; i += 256) {
            const float4 a = raw[3 * i];
            const float4 c = raw[3 * i + 1];
            const float4 d = raw[3 * i + 2];
            // points 4i..4i+3: (a.x,a.y,a.z) (a.w,c.x,c.y) (c.z,c.w,d.x) (d.y,d.z,d.w)
            tx[i] = make_float4(a.x, a.w, c.z, d.y);
            ty[i] = make_float4(a.y, c.x, c.w, d.z);
            tz[i] = make_float4(a.z, c.y, d.x, d.w);
            ts[i] = make_float4(sq3(a.x, a.y, a.z), sq3(a.w, c.x, c.y),
                                sq3(c.z, c.w, d.x), sq3(d.y, d.z, d.w));
        }
    }
    __syncthreads();

    const float xn  = sx[n];
    const float yn  = sy[n];
    const float zn  = sz[n];
    const float sqn = ssq[n];

    const float4* X  = reinterpret_cast<const float4*>(sx);
    const float4* Y  = reinterpret_cast<const float4*>(sy);
    const float4* Z  = reinterpret_cast<const float4*>(sz);
    const float4* SQ = reinterpret_cast<const float4*>(ssq);

    int cnt = 0;
    const unsigned lmask = (1u << lane) - 1u;
    int* hits = sh_hits[warp];

    // Prologue: A <- chunk 0, B <- chunk 128; meta for chunk 0.
    float4 ax = X[lane],      ay = Y[lane],      az = Z[lane],      aq = SQ[lane];
    float4 bx = X[lane + 32], by = Y[lane + 32], bz = Z[lane + 32], bq = SQ[lane + 32];
    unsigned nibA = eval_nib(xn, yn, zn, sqn, ax, ay, az, aq);
    unsigned a0 = __ballot_sync(0xffffffffu, nibA & 1u);
    unsigned a1 = __ballot_sync(0xffffffffu, nibA & 2u);
    unsigned a2 = __ballot_sync(0xffffffffu, nibA & 4u);
    unsigned a3 = __ballot_sync(0xffffffffu, nibA & 8u);

    for (int base = 0; ; ) {
        // phase 1: load->A(base+256), eval+ballot B(base+128), bookkeep base (A-meta)
        {
            const int nb2 = base + 256;
            unsigned nibB;
            if (nb2 < NP) {
                const int f = (nb2 >> 2) + lane;
                // evaluate B BEFORE overwriting nothing (A is dead meta-wise)
                nibB = eval_nib(xn, yn, zn, sqn, bx, by, bz, bq);
                ax = X[f]; ay = Y[f]; az = Z[f]; aq = SQ[f];
            } else {
                nibB = eval_nib(xn, yn, zn, sqn, bx, by, bz, bq);
            }
            const unsigned d0 = __ballot_sync(0xffffffffu, nibB & 1u);
            const unsigned d1 = __ballot_sync(0xffffffffu, nibB & 2u);
            const unsigned d2 = __ballot_sync(0xffffffffu, nibB & 4u);
            const unsigned d3 = __ballot_sync(0xffffffffu, nibB & 8u);
            if (bookkeep(base, lane, lmask, nibA, a0, a1, a2, a3, cnt, hits)) break;
            base += 128;
            if (base >= NP) break;
            nibA = nibB; a0 = d0; a1 = d1; a2 = d2; a3 = d3;  // meta rotate
        }
        // phase 2: load->B(base+256), eval+ballot A(base+128), bookkeep base (rotated meta)
        {
            const int nb2 = base + 256;
            unsigned nibB;
            if (nb2 < NP) {
                const int f = (nb2 >> 2) + lane;
                nibB = eval_nib(xn, yn, zn, sqn, ax, ay, az, aq);
                bx = X[f]; by = Y[f]; bz = Z[f]; bq = SQ[f];
            } else {
                nibB = eval_nib(xn, yn, zn, sqn, ax, ay, az, aq);
            }
            const unsigned d0 = __ballot_sync(0xffffffffu, nibB & 1u);
            const unsigned d1 = __ballot_sync(0xffffffffu, nibB & 2u);
            const unsigned d2 = __ballot_sync(0xffffffffu, nibB & 4u);
            const unsigned d3 = __ballot_sync(0xffffffffu, nibB & 8u);
            if (bookkeep(base, lane, lmask, nibA, a0, a1, a2, a3, cnt, hits)) break;
            base += 128;
            if (base >= NP) break;
            nibA = nibB; a0 = d0; a1 = d1; a2 = d2; a3 = d3;
        }
    }
    __syncwarp();

    if (lane < KOUT) {
        const int h0 = hits[0];                  // center = first (smallest-index) hit
        int v = h0;                              // (self-hit guarantees cnt >= 1)
        if (lane > 0) {
            const int j = lane + 15;             // annular region: hits 16..30
            if (j < cnt) v = hits[j];            // else padded with center
        }
        g_ids[(q << 4) + lane] = v;
    }
}

__global__ __launch_bounds__(256) void gather_kernel(const float* __restrict__ xyz,
                                                     const float* __restrict__ feat,
                                                     float* __restrict__ out) {
    const int t  = blockIdx.x * 256 + threadIdx.x;    // 0..65535 : b(2)|n(12)|k4(2)
    const int k4 = t & 3;
    const int n  = (t >> 2) & (NP - 1);
    const int b  = t >> 14;
    const int bb = b << 12;
    const int4 id4 = reinterpret_cast<const int4*>(g_ids)[t];   // ids for k=4*k4..+3
    const int o4 = (n << 2) + k4;                     // float4 index within a channel plane

    // dilated_xyz: [B, 3, N, K]  (channel plane = 65536 floats = 16384 float4)
    const float* xb = xyz + 3 * bb;
    const float x0 = xb[3 * id4.x], y0 = xb[3 * id4.x + 1], z0 = xb[3 * id4.x + 2];
    const float x1 = xb[3 * id4.y], y1 = xb[3 * id4.y + 1], z1 = xb[3 * id4.y + 2];
    const float x2 = xb[3 * id4.z], y2 = xb[3 * id4.z + 1], z2 = xb[3 * id4.z + 2];
    const float x3 = xb[3 * id4.w], y3 = xb[3 * id4.w + 1], z3 = xb[3 * id4.w + 2];
    float4* o = reinterpret_cast<float4*>(out);
    o[((b * 3 + 0) << 14) + o4] = make_float4(x0, x1, x2, x3);
    o[((b * 3 + 1) << 14) + o4] = make_float4(y0, y1, y2, y3);
    o[((b * 3 + 2) << 14) + o4] = make_float4(z0, z1, z2, z3);

    // dilated_feature: [B, 64, N, K] after the xyz block (12 planes)
    const float4* f0 = reinterpret_cast<const float4*>(feat) + ((bb + id4.x) << 4);
    const float4* f1 = reinterpret_cast<const float4*>(feat) + ((bb + id4.y) << 4);
    const float4* f2 = reinterpret_cast<const float4*>(feat) + ((bb + id4.z) << 4);
    const float4* f3 = reinterpret_cast<const float4*>(feat) + ((bb + id4.w) << 4);
    float4* of = o + ((12 + b * 64) << 14) + o4;
    #pragma unroll
    for (int c4 = 0; c4 < 16; ++c4) {
        const float4 v0 = f0[c4], v1 = f1[c4], v2 = f2[c4], v3 = f3[c4];
        of[(4 * c4 + 0) << 14] = make_float4(v0.x, v1.x, v2.x, v3.x);
        of[(4 * c4 + 1) << 14] = make_float4(v0.y, v1.y, v2.y, v3.y);
        of[(4 * c4 + 2) << 14] = make_float4(v0.z, v1.z, v2.z, v3.z);
        of[(4 * c4 + 3) << 14] = make_float4(v0.w, v1.w, v2.w, v3.w);
    }
}

extern "C" void kernel_launch(void* const* d_in, const int* in_sizes, int n_in,
                              void* d_out, int out_size) {
    const float* xyz  = (const float*)d_in[0];
    const float* feat = (const float*)d_in[1];
    float* out = (float*)d_out;

    cudaFuncSetAttribute(query_kernel,
                         cudaFuncAttributeMaxDynamicSharedMemorySize, 4 * NP * 4);

    query_kernel<<<(NB * NP) / 8, 256, 4 * NP * 4>>>(xyz);
    gather_kernel<<<(NB * NP * KOUT / 4) / 256, 256>>>(xyz, feat, out);
}

// round 5
// speedup vs baseline: 1.1410x; 1.1410x over previous
#include <cuda_runtime.h>

// AnnularDilatedKNN: B=4, N=4096, C=64, SAMPLE=16, DILATED_RATE=2 -> NSAMPLE=32, K_out=16
// radius^2 = 256.
//
// R4 changes (occupancy round):
//  - query: 512 threads/block (16 queries), smem carveout hint -> 12 warps/SMSP
//  - gather split: xyz (tiny kernel) + feature gather re-tiled to
//    thread-per-(b,n,k4,cq): 4x threads, 4 cq-threads read adjacent 64B
//    quarters of one feature row (coalesced), writes stay full-line coalesced.
// Per-candidate arithmetic + extraction bookkeeping byte-identical to the
// rel_err=0.0 verified kernels.

#define NB   4
#define NP   4096
#define KOUT 16
#define QWARPS 16   // queries (warps) per query block

__device__ int g_ids[NB * NP * KOUT];

__device__ __forceinline__ float sq3(float x, float y, float z) {
    // jnp.sum(xyz*xyz, -1): left-to-right, separately rounded products (no fma).
    return __fadd_rn(__fadd_rn(__fmul_rn(x, x), __fmul_rn(y, y)), __fmul_rn(z, z));
}

// nib evaluation: byte-identical arithmetic to the verified kernels.
__device__ __forceinline__ unsigned eval_nib(float xn, float yn, float zn, float sqn,
                                             const float4& x4, const float4& y4,
                                             const float4& z4, const float4& s4) {
    unsigned nib = 0;
    float dot, d2;
    dot = fmaf(zn, z4.x, fmaf(yn, y4.x, __fmul_rn(xn, x4.x)));
    d2  = __fsub_rn(__fadd_rn(sqn, s4.x), __fmul_rn(2.0f, dot));
    if (d2 < 256.0f) nib |= 1u;
    dot = fmaf(zn, z4.y, fmaf(yn, y4.y, __fmul_rn(xn, x4.y)));
    d2  = __fsub_rn(__fadd_rn(sqn, s4.y), __fmul_rn(2.0f, dot));
    if (d2 < 256.0f) nib |= 2u;
    dot = fmaf(zn, z4.z, fmaf(yn, y4.z, __fmul_rn(xn, x4.z)));
    d2  = __fsub_rn(__fadd_rn(sqn, s4.z), __fmul_rn(2.0f, dot));
    if (d2 < 256.0f) nib |= 4u;
    dot = fmaf(zn, z4.w, fmaf(yn, y4.w, __fmul_rn(xn, x4.w)));
    d2  = __fsub_rn(__fadd_rn(sqn, s4.w), __fmul_rn(2.0f, dot));
    if (d2 < 256.0f) nib |= 8u;
    return nib;
}

// Bookkeeping for one chunk. Returns true when >=31 hits found (uniform).
__device__ __forceinline__ bool bookkeep(int base, int lane, unsigned lmask,
                                         unsigned nib, unsigned b0, unsigned b1,
                                         unsigned b2, unsigned b3,
                                         int& cnt, int* hits) {
    if (nib) {
        int p = cnt + __popc(b0 & lmask) + __popc(b1 & lmask)
                    + __popc(b2 & lmask) + __popc(b3 & lmask);
        const int c0 = base + (lane << 2);
        if (nib & 1u) { if (p < 31) hits[p] = c0;     ++p; }
        if (nib & 2u) { if (p < 31) hits[p] = c0 + 1; ++p; }
        if (nib & 4u) { if (p < 31) hits[p] = c0 + 2; ++p; }
        if (nib & 8u) { if (p < 31) hits[p] = c0 + 3; ++p; }
    }
    cnt += __popc(b0) + __popc(b1) + __popc(b2) + __popc(b3);
    return cnt >= 31;
}

__global__ __launch_bounds__(32 * QWARPS) void query_kernel(const float* __restrict__ xyz) {
    extern __shared__ float sm[];
    float* sx  = sm;
    float* sy  = sm + NP;
    float* sz  = sm + 2 * NP;
    float* ssq = sm + 3 * NP;
    __shared__ int sh_hits[QWARPS][32];

    const int warp = threadIdx.x >> 5;
    const int lane = threadIdx.x & 31;
    const int q = blockIdx.x * QWARPS + warp;    // global query id
    const int b = q >> 12;                        // all warps of a block share b
    const int n = q & (NP - 1);

    // Stage batch SoA + sq straight from raw xyz [N,3] (fused prep).
    {
        const float4* raw = reinterpret_cast<const float4*>(xyz) + b * (NP * 3 / 4);
        float4* tx = reinterpret_cast<float4*>(sx);
        float4* ty = reinterpret_cast<float4*>(sy);
        float4* tz = reinterpret_cast<float4*>(sz);
        float4* ts = reinterpret_cast<float4*>(ssq);
        for (int i = threadIdx.x; i < NP / 4; i += 32 * QWARPS) {
            const float4 a = raw[3 * i];
            const float4 c = raw[3 * i + 1];
            const float4 d = raw[3 * i + 2];
            // points 4i..4i+3: (a.x,a.y,a.z) (a.w,c.x,c.y) (c.z,c.w,d.x) (d.y,d.z,d.w)
            tx[i] = make_float4(a.x, a.w, c.z, d.y);
            ty[i] = make_float4(a.y, c.x, c.w, d.z);
            tz[i] = make_float4(a.z, c.y, d.x, d.w);
            ts[i] = make_float4(sq3(a.x, a.y, a.z), sq3(a.w, c.x, c.y),
                                sq3(c.z, c.w, d.x), sq3(d.y, d.z, d.w));
        }
    }
    __syncthreads();

    const float xn  = sx[n];
    const float yn  = sy[n];
    const float zn  = sz[n];
    const float sqn = ssq[n];

    const float4* X  = reinterpret_cast<const float4*>(sx);
    const float4* Y  = reinterpret_cast<const float4*>(sy);
    const float4* Z  = reinterpret_cast<const float4*>(sz);
    const float4* SQ = reinterpret_cast<const float4*>(ssq);

    int cnt = 0;
    const unsigned lmask = (1u << lane) - 1u;
    int* hits = sh_hits[warp];

    // Prologue: A <- chunk 0, B <- chunk 128; meta for chunk 0.
    float4 ax = X[lane],      ay = Y[lane],      az = Z[lane],      aq = SQ[lane];
    float4 bx = X[lane + 32], by = Y[lane + 32], bz = Z[lane + 32], bq = SQ[lane + 32];
    unsigned nibA = eval_nib(xn, yn, zn, sqn, ax, ay, az, aq);
    unsigned a0 = __ballot_sync(0xffffffffu, nibA & 1u);
    unsigned a1 = __ballot_sync(0xffffffffu, nibA & 2u);
    unsigned a2 = __ballot_sync(0xffffffffu, nibA & 4u);
    unsigned a3 = __ballot_sync(0xffffffffu, nibA & 8u);

    for (int base = 0; ; ) {
        // phase 1: load->A(base+256), eval+ballot B(base+128), bookkeep base (A-meta)
        {
            const int nb2 = base + 256;
            unsigned nibB = eval_nib(xn, yn, zn, sqn, bx, by, bz, bq);
            if (nb2 < NP) {
                const int f = (nb2 >> 2) + lane;
                ax = X[f]; ay = Y[f]; az = Z[f]; aq = SQ[f];
            }
            const unsigned d0 = __ballot_sync(0xffffffffu, nibB & 1u);
            const unsigned d1 = __ballot_sync(0xffffffffu, nibB & 2u);
            const unsigned d2 = __ballot_sync(0xffffffffu, nibB & 4u);
            const unsigned d3 = __ballot_sync(0xffffffffu, nibB & 8u);
            if (bookkeep(base, lane, lmask, nibA, a0, a1, a2, a3, cnt, hits)) break;
            base += 128;
            if (base >= NP) break;
            nibA = nibB; a0 = d0; a1 = d1; a2 = d2; a3 = d3;  // meta rotate
        }
        // phase 2: load->B(base+256), eval+ballot A(base+128), bookkeep base (rotated meta)
        {
            const int nb2 = base + 256;
            unsigned nibB = eval_nib(xn, yn, zn, sqn, ax, ay, az, aq);
            if (nb2 < NP) {
                const int f = (nb2 >> 2) + lane;
                bx = X[f]; by = Y[f]; bz = Z[f]; bq = SQ[f];
            }
            const unsigned d0 = __ballot_sync(0xffffffffu, nibB & 1u);
            const unsigned d1 = __ballot_sync(0xffffffffu, nibB & 2u);
            const unsigned d2 = __ballot_sync(0xffffffffu, nibB & 4u);
            const unsigned d3 = __ballot_sync(0xffffffffu, nibB & 8u);
            if (bookkeep(base, lane, lmask, nibA, a0, a1, a2, a3, cnt, hits)) break;
            base += 128;
            if (base >= NP) break;
            nibA = nibB; a0 = d0; a1 = d1; a2 = d2; a3 = d3;
        }
    }
    __syncwarp();

    if (lane < KOUT) {
        const int h0 = hits[0];                  // center = first (smallest-index) hit
        int v = h0;                              // (self-hit guarantees cnt >= 1)
        if (lane > 0) {
            const int j = lane + 15;             // annular region: hits 16..30
            if (j < cnt) v = hits[j];            // else padded with center
        }
        g_ids[(q << 4) + lane] = v;
    }
}

// xyz gather: thread per (b,n,k4). 3 planes, coalesced float4 writes.
__global__ __launch_bounds__(256) void gather_xyz_kernel(const float* __restrict__ xyz,
                                                         float* __restrict__ out) {
    const int t  = blockIdx.x * 256 + threadIdx.x;    // 0..16383 : b(2)|n(12)
    const int k4 = t & 3;
    const int n  = (t >> 2) & (NP - 1);
    const int b  = t >> 14;
    const int bb = b << 12;
    const int4 id4 = reinterpret_cast<const int4*>(g_ids)[t];
    const int o4 = (n << 2) + k4;

    const float* xb = xyz + 3 * bb;
    const float x0 = xb[3 * id4.x], y0 = xb[3 * id4.x + 1], z0 = xb[3 * id4.x + 2];
    const float x1 = xb[3 * id4.y], y1 = xb[3 * id4.y + 1], z1 = xb[3 * id4.y + 2];
    const float x2 = xb[3 * id4.z], y2 = xb[3 * id4.z + 1], z2 = xb[3 * id4.z + 2];
    const float x3 = xb[3 * id4.w], y3 = xb[3 * id4.w + 1], z3 = xb[3 * id4.w + 2];
    float4* o = reinterpret_cast<float4*>(out);
    o[((b * 3 + 0) << 14) + o4] = make_float4(x0, x1, x2, x3);
    o[((b * 3 + 1) << 14) + o4] = make_float4(y0, y1, y2, y3);
    o[((b * 3 + 2) << 14) + o4] = make_float4(z0, z1, z2, z3);
}

// feature gather: thread per (b,n,k4,cq). cq = quarter of the 64-channel row.
// warp layout ...n(1)|k4(2)|cq(2): the 4 cq-threads of a point read adjacent
// 64B quarters of its 256B row (coalesced); writes are 128B-line coalesced.
__global__ __launch_bounds__(256) void gather_feat_kernel(const float* __restrict__ feat,
                                                          float* __restrict__ out) {
    const int t  = blockIdx.x * 256 + threadIdx.x;    // 0..262143 : b(2)|n(12)|k4(2)|cq(2)
    const int cq = t & 3;
    const int k4 = (t >> 2) & 3;
    const int n  = (t >> 4) & (NP - 1);
    const int b  = t >> 16;
    const int bb = b << 12;
    const int4 id4 = reinterpret_cast<const int4*>(g_ids)[((bb + n) << 2) + k4];
    const int o4 = (n << 2) + k4;

    const float4* f0 = reinterpret_cast<const float4*>(feat) + ((bb + id4.x) << 4) + (cq << 2);
    const float4* f1 = reinterpret_cast<const float4*>(feat) + ((bb + id4.y) << 4) + (cq << 2);
    const float4* f2 = reinterpret_cast<const float4*>(feat) + ((bb + id4.z) << 4) + (cq << 2);
    const float4* f3 = reinterpret_cast<const float4*>(feat) + ((bb + id4.w) << 4) + (cq << 2);

    float4* of = reinterpret_cast<float4*>(out) + ((12 + b * 64 + (cq << 4)) << 14) + o4;
    #pragma unroll
    for (int j = 0; j < 4; ++j) {                     // channels 16*cq+4j .. +3
        const float4 v0 = f0[j], v1 = f1[j], v2 = f2[j], v3 = f3[j];
        of[(4 * j + 0) << 14] = make_float4(v0.x, v1.x, v2.x, v3.x);
        of[(4 * j + 1) << 14] = make_float4(v0.y, v1.y, v2.y, v3.y);
        of[(4 * j + 2) << 14] = make_float4(v0.z, v1.z, v2.z, v3.z);
        of[(4 * j + 3) << 14] = make_float4(v0.w, v1.w, v2.w, v3.w);
    }
}

extern "C" void kernel_launch(void* const* d_in, const int* in_sizes, int n_in,
                              void* d_out, int out_size) {
    const float* xyz  = (const float*)d_in[0];
    const float* feat = (const float*)d_in[1];
    float* out = (float*)d_out;

    cudaFuncSetAttribute(query_kernel,
                         cudaFuncAttributeMaxDynamicSharedMemorySize, 4 * NP * 4);
    cudaFuncSetAttribute(query_kernel,
                         cudaFuncAttributePreferredSharedMemoryCarveout, 100);

    query_kernel<<<(NB * NP) / QWARPS, 32 * QWARPS, 4 * NP * 4>>>(xyz);
    gather_xyz_kernel<<<(NB * NP * 4) / 256, 256>>>(xyz, out);
    gather_feat_kernel<<<(NB * NP * KOUT) / 256, 256>>>(feat, out);
}